// round 4
// baseline (speedup 1.0000x reference)
#include <cuda_runtime.h>
#include <math.h>

#define NS 4096
#define NT 4096
#define NPDE 296                 // 148 row-chunks x 2 col-halves = 2 blocks/SM exactly
#define W_PDE (1.0 / (4094.0 * 4094.0))
#define W_EDGE_F ((float)(10.0 / 4096.0))

__device__ double g_part[NPDE];
__device__ unsigned int g_count = 0;

__inline__ __device__ float warp_reduce(float v) {
    #pragma unroll
    for (int o = 16; o > 0; o >>= 1) v += __shfl_down_sync(0xffffffffu, v, o);
    return v;
}
__inline__ __device__ double warp_reduce_d(double v) {
    #pragma unroll
    for (int o = 16; o > 0; o >>= 1) v += __shfl_down_sync(0xffffffffu, v, o);
    return v;
}

// One stencil row: 4 elements. cstv = {A1, A2, H, A3} for this row.
__device__ __forceinline__ void accum_row(const float4 cstv,
                                          const float4 vm, const float4 vc, const float4 vp,
                                          float left, float right,
                                          float m0, float m3, float inv2dt, float& part)
{
    const float A1 = cstv.x, A2 = cstv.y, H = cstv.z, A3 = cstv.w;
    const float vls[6] = {left, vc.x, vc.y, vc.z, vc.w, right};
    const float vmm[4] = {vm.x, vm.y, vm.z, vm.w};
    const float vpp[4] = {vp.x, vp.y, vp.z, vp.w};
    #pragma unroll
    for (int e = 0; e < 4; e++) {
        const float v0   = vls[e + 1];
        const float s    = vpp[e] + vmm[e];
        const float Vuu  = fmaf(-2.0f, v0, s);          // raw 2nd diff (unscaled)
        const float Vu   = vpp[e] - vmm[e];             // raw 1st diff (unscaled)
        const float raw  = fmaf(Vuu, A1, -(Vu * A2));   // = Sn^2 * VSS (unclipped)
        const float t2c  = fminf(fmaxf(raw, -H), H);    // = Sn^2 * clip(VSS, +-100)
        const float dvc  = vls[e + 2] - vls[e];
        float t = fmaf(dvc, inv2dt, -t2c);              // Vt - Sn^2*VSS
        t = fmaf(-A3, Vu, t);                           // - alpha*Sn*VS
        const float res = fmaf(2.5f, v0, t);            // + alpha*V
        const float r2  = res * res;
        const float m = (e == 0) ? m0 : ((e == 3) ? m3 : 1.0f);
        part = fmaf(r2, m, part);
    }
}

// Column-neighbor exchange via warp shuffle; only warp-boundary lanes load.
__device__ __forceinline__ void halo(const float4 vc, bool needL, bool needR,
                                     const float* pL, const float* pR, long roff,
                                     float& left, float& right)
{
    left  = __shfl_up_sync(0xffffffffu, vc.w, 1);
    right = __shfl_down_sync(0xffffffffu, vc.x, 1);
    if (needL) left  = __ldg(pL + roff);
    if (needR) right = __ldg(pR + roff);
}

__global__ void __launch_bounds__(512, 2)
loss_kernel(const float* __restrict__ V, float* __restrict__ out,
            float c1f, float c2f, float su_coef, float suu_coef, float inv2dt)
{
    const int tid  = threadIdx.x;
    const int lane = tid & 31;
    const int bid  = blockIdx.x;
    const int rc   = bid >> 1;          // row chunk 0..147
    const int cb   = bid & 1;           // column half

    __shared__ float4 cst[28];
    __shared__ float s1[16], s2[16];
    __shared__ unsigned s_old;

    // balanced rows: chunks 0..97 get 28 rows, 98..147 get 27 (total 4094)
    const int i0    = 1 + rc * 27 + min(rc, 98);
    const int nrows = 27 + (rc < 98 ? 1 : 0);

    // ---- per-row folded constants into shared ----
    if (tid < nrows) {
        const int   i  = i0 + tid;
        const float u  = (float)i * (1.0f / 4095.0f);
        const float L  = c2f * u + c1f * (1.0f - u);
        const float S  = 100.0f + 30.0f * (L * L * L * (1.0f / 6.0f) + L);
        const float Sn = S * (1.0f / 300.0f);
        const float Sun  = su_coef * (0.5f * L * L + 1.0f) * (1.0f / 300.0f);
        const float Suun = (suu_coef * L) * (1.0f / 300.0f);
        const float invSun  = 1.0f / Sun;
        const float invSun2 = invSun * invSun;
        const float Sn2 = Sn * Sn;
        float4 cc;
        cc.x = 16769025.0f * Sn2 * invSun2;                 // A1
        cc.y = 2047.5f * Suun * Sn2 * invSun2 * invSun;     // A2
        cc.z = 100.0f * Sn2;                                // H
        cc.w = 2.5f * Sn * 2047.5f * invSun;                // A3
        cst[tid] = cc;
    }

    // ---- distributed BC/TC edge losses (pre-weighted), ~28 elems/block ----
    float edge = 0.0f;
    {
        const int g = bid * 28 + tid;
        if (tid < 28 && g < 2 * NT) {
            if (g < NT) {
                const float t = (float)g * (1.0f / 4095.0f);
                const float target = 1.0f - (100.0f * expf(-0.05f * (1.0f - t))) * (1.0f / 300.0f);
                const float d = V[(size_t)(NS - 1) * NT + g] - target;
                edge = W_EDGE_F * (d * d);
            } else {
                const int   i2 = g - NT;
                const float u  = (float)i2 * (1.0f / 4095.0f);
                const float x  = 50.0f * (u - 0.33333334f);
                const float sp = (fmaxf(x, 0.0f) + log1pf(expf(-fabsf(x)))) * (1.0f / 50.0f);
                const float d  = V[(size_t)i2 * NT + (NT - 1)] - sp;
                const float ad = fabsf(d);
                const float h  = (ad < 0.01f) ? 0.5f * d * d : 0.01f * (ad - 0.005f);
                edge = W_EDGE_F * h;
            }
        }
    }
    __syncthreads();

    // ---- PDE residual: rolling 3-row register stencil, 4-row unroll ----
    const int jb = (cb * 512 + tid) * 4;
    const float m0 = (jb == 0)    ? 0.0f : 1.0f;
    const float m3 = (jb == 4092) ? 0.0f : 1.0f;
    // warp-boundary halo loads: only lane 0 / lane 31 (and not at grid edges)
    const bool needL = (lane == 0)  && (jb != 0);
    const bool needR = (lane == 31) && (jb != 4092);
    const float* pL = V + (size_t)i0 * NT + (jb - 1);   // valid only if needL
    const float* pR = V + (size_t)i0 * NT + (jb + 4);   // valid only if needR

    const float* base = V + (size_t)(i0 - 1) * NT + jb;
    float4 vm = *(const float4*)base;
    float4 vc = *(const float4*)(base + NT);

    float part = 0.0f;
    int r = 0;
    for (; r + 4 <= nrows; r += 4) {
        const float* p = base + (size_t)(r + 2) * NT;
        const float4 p0 = *(const float4*)(p);
        const float4 p1 = *(const float4*)(p + NT);
        const float4 p2 = *(const float4*)(p + 2 * NT);
        const float4 p3 = *(const float4*)(p + 3 * NT);
        float lf, rt;
        const long ro = (long)r * NT;
        halo(vc, needL, needR, pL, pR, ro, lf, rt);
        accum_row(cst[r],     vm, vc, p0, lf, rt, m0, m3, inv2dt, part);
        halo(p0, needL, needR, pL, pR, ro + NT, lf, rt);
        accum_row(cst[r + 1], vc, p0, p1, lf, rt, m0, m3, inv2dt, part);
        halo(p1, needL, needR, pL, pR, ro + 2 * NT, lf, rt);
        accum_row(cst[r + 2], p0, p1, p2, lf, rt, m0, m3, inv2dt, part);
        halo(p2, needL, needR, pL, pR, ro + 3 * NT, lf, rt);
        accum_row(cst[r + 3], p1, p2, p3, lf, rt, m0, m3, inv2dt, part);
        vm = p2; vc = p3;
    }
    for (; r < nrows; r++) {
        const float4 p0 = *(const float4*)(base + (size_t)(r + 2) * NT);
        float lf, rt;
        halo(vc, needL, needR, pL, pR, (long)r * NT, lf, rt);
        accum_row(cst[r], vm, vc, p0, lf, rt, m0, m3, inv2dt, part);
        vm = vc; vc = p0;
    }

    // ---- block reduce (raw pde sum + pre-weighted edge sum) ----
    part = warp_reduce(part);
    edge = warp_reduce(edge);
    if ((tid & 31) == 0) { s1[tid >> 5] = part; s2[tid >> 5] = edge; }
    __syncthreads();
    if (tid < 32) {
        float vpp = (tid < 16) ? s1[tid] : 0.0f;
        float vee = (tid < 16) ? s2[tid] : 0.0f;
        vpp = warp_reduce(vpp);
        vee = warp_reduce(vee);
        if (tid == 0) {
            g_part[bid] = (double)vpp * W_PDE + (double)vee;
            __threadfence();
            s_old = atomicAdd(&g_count, 1u);
        }
    }
    __syncthreads();

    // ---- last block finishes: plain sum of 296 doubles ----
    if (s_old == NPDE - 1) {
        __threadfence();
        double v = (tid < NPDE) ? g_part[tid] : 0.0;
        v = warp_reduce_d(v);
        __shared__ double sd[16];
        if ((tid & 31) == 0) sd[tid >> 5] = v;
        __syncthreads();
        if (tid < 32) {
            double t2 = (tid < 16) ? sd[tid] : 0.0;
            t2 = warp_reduce_d(t2);
            if (tid == 0) {
                out[0] = (float)t2;
                g_count = 0;   // reset for next graph replay (deterministic)
            }
        }
    }
}

static double solve_depressed_cubic(double Q) {
    const double p = 6.0;             // CHI
    const double q = 6.0 * Q;
    const double sp = sqrt(p);
    double arg = fabs(q) / (2.0 * p * sp / (3.0 * sqrt(3.0)));
    if (arg < 1.0) arg = 1.0;
    const double c = 2.0 * sp * cosh(acosh(arg) / 3.0);
    return (q >= 0.0) ? -c : c;
}

extern "C" void kernel_launch(void* const* d_in, const int* in_sizes, int n_in,
                              void* d_out, int out_size)
{
    const float* V = (const float*)d_in[0];
    float* out = (float*)d_out;

    const double C1 = solve_depressed_cubic((100.0 - 0.0) / 30.0);
    const double C2 = solve_depressed_cubic((100.0 - 300.0) / 30.0);
    const double dL = C2 - C1;
    const float c1f = (float)C1;
    const float c2f = (float)C2;
    const float su_coef  = (float)(30.0 * dL);        // ALPHA_STR * dL
    const float suu_coef = (float)(30.0 * dL * dL);   // ALPHA_STR * dL^2
    const double TAU_MAX = 0.5 * 0.2 * 0.2 * 1.0;     // 0.02
    const double DT_NORM = TAU_MAX / (double)(NT - 1);
    const float inv2dt = (float)(1.0 / (2.0 * DT_NORM));

    loss_kernel<<<NPDE, 512>>>(V, out, c1f, c2f, su_coef, suu_coef, inv2dt);
}

// round 5
// speedup vs baseline: 1.0118x; 1.0118x over previous
#include <cuda_runtime.h>
#include <math.h>

#define NS 4096
#define NT 4096
#define NRC 222                  // row chunks
#define NPDE (NRC * 2)           // 444 = 148 SMs x 3 blocks
#define MAXROWS 19
#define W_PDE (1.0 / (4094.0 * 4094.0))
#define W_EDGE_F ((float)(10.0 / 4096.0))

__device__ double g_part[NPDE];
__device__ unsigned int g_count = 0;

__inline__ __device__ float warp_reduce(float v) {
    #pragma unroll
    for (int o = 16; o > 0; o >>= 1) v += __shfl_down_sync(0xffffffffu, v, o);
    return v;
}
__inline__ __device__ double warp_reduce_d(double v) {
    #pragma unroll
    for (int o = 16; o > 0; o >>= 1) v += __shfl_down_sync(0xffffffffu, v, o);
    return v;
}

// One stencil row: 4 elements. cstv = {A1, A2, H, A3} for this row.
__device__ __forceinline__ void accum_row(const float4 cstv,
                                          const float4 vm, const float4 vc, const float4 vp,
                                          float left, float right,
                                          float m0, float m3, float inv2dt, float& part)
{
    const float A1 = cstv.x, A2 = cstv.y, H = cstv.z, A3 = cstv.w;
    const float vls[6] = {left, vc.x, vc.y, vc.z, vc.w, right};
    const float vmm[4] = {vm.x, vm.y, vm.z, vm.w};
    const float vpp[4] = {vp.x, vp.y, vp.z, vp.w};
    #pragma unroll
    for (int e = 0; e < 4; e++) {
        const float v0   = vls[e + 1];
        const float s    = vpp[e] + vmm[e];
        const float Vuu  = fmaf(-2.0f, v0, s);
        const float Vu   = vpp[e] - vmm[e];
        const float raw  = fmaf(Vuu, A1, -(Vu * A2));   // Sn^2 * VSS (unclipped)
        const float t2c  = fminf(fmaxf(raw, -H), H);
        const float dvc  = vls[e + 2] - vls[e];
        float t = fmaf(dvc, inv2dt, -t2c);
        t = fmaf(-A3, Vu, t);
        const float res = fmaf(2.5f, v0, t);
        const float r2  = res * res;
        const float m = (e == 0) ? m0 : ((e == 3) ? m3 : 1.0f);
        part = fmaf(r2, m, part);
    }
}

__device__ __forceinline__ void halo(const float4 vc, bool needL, bool needR,
                                     const float* pL, const float* pR, long roff,
                                     float& left, float& right)
{
    left  = __shfl_up_sync(0xffffffffu, vc.w, 1);
    right = __shfl_down_sync(0xffffffffu, vc.x, 1);
    if (needL) left  = __ldg(pL + roff);
    if (needR) right = __ldg(pR + roff);
}

__global__ void __launch_bounds__(512, 3)
loss_kernel(const float* __restrict__ V, float* __restrict__ out,
            float c1f, float c2f, float su_coef, float suu_coef, float inv2dt)
{
    const int tid  = threadIdx.x;
    const int lane = tid & 31;
    const int bid  = blockIdx.x;
    const int rc   = bid >> 1;          // row chunk 0..221
    const int cb   = bid & 1;           // column half

    __shared__ float4 cst[MAXROWS];
    __shared__ float s1[16], s2[16];
    __shared__ unsigned s_old;

    // balanced rows: chunks 0..97 get 19 rows, 98..221 get 18 (total 4094)
    const int i0    = 1 + rc * 18 + min(rc, 98);
    const int nrows = 18 + (rc < 98 ? 1 : 0);

    // ---- per-row folded constants into shared ----
    if (tid < nrows) {
        const int   i  = i0 + tid;
        const float u  = (float)i * (1.0f / 4095.0f);
        const float L  = c2f * u + c1f * (1.0f - u);
        const float S  = 100.0f + 30.0f * (L * L * L * (1.0f / 6.0f) + L);
        const float Sn = S * (1.0f / 300.0f);
        const float Sun  = su_coef * (0.5f * L * L + 1.0f) * (1.0f / 300.0f);
        const float Suun = (suu_coef * L) * (1.0f / 300.0f);
        const float invSun  = 1.0f / Sun;
        const float invSun2 = invSun * invSun;
        const float Sn2 = Sn * Sn;
        float4 cc;
        cc.x = 16769025.0f * Sn2 * invSun2;                 // A1
        cc.y = 2047.5f * Suun * Sn2 * invSun2 * invSun;     // A2
        cc.z = 100.0f * Sn2;                                // H
        cc.w = 2.5f * Sn * 2047.5f * invSun;                // A3
        cst[tid] = cc;
    }

    // ---- distributed BC/TC edge losses (pre-weighted), ~19 elems/block ----
    float edge = 0.0f;
    {
        const int g = bid * MAXROWS + tid;
        if (tid < MAXROWS && g < 2 * NT) {
            if (g < NT) {
                const float t = (float)g * (1.0f / 4095.0f);
                const float target = 1.0f - (100.0f * expf(-0.05f * (1.0f - t))) * (1.0f / 300.0f);
                const float d = V[(size_t)(NS - 1) * NT + g] - target;
                edge = W_EDGE_F * (d * d);
            } else {
                const int   i2 = g - NT;
                const float u  = (float)i2 * (1.0f / 4095.0f);
                const float x  = 50.0f * (u - 0.33333334f);
                const float sp = (fmaxf(x, 0.0f) + log1pf(expf(-fabsf(x)))) * (1.0f / 50.0f);
                const float d  = V[(size_t)i2 * NT + (NT - 1)] - sp;
                const float ad = fabsf(d);
                const float h  = (ad < 0.01f) ? 0.5f * d * d : 0.01f * (ad - 0.005f);
                edge = W_EDGE_F * h;
            }
        }
    }
    __syncthreads();

    // ---- PDE residual: rolling 3-row register stencil, 2-row unroll ----
    const int jb = (cb * 512 + tid) * 4;
    const float m0 = (jb == 0)    ? 0.0f : 1.0f;
    const float m3 = (jb == 4092) ? 0.0f : 1.0f;
    const bool needL = (lane == 0)  && (jb != 0);
    const bool needR = (lane == 31) && (jb != 4092);
    const float* pL = V + (size_t)i0 * NT + (jb - 1);
    const float* pR = V + (size_t)i0 * NT + (jb + 4);

    const float* base = V + (size_t)(i0 - 1) * NT + jb;
    float4 vm = *(const float4*)base;
    float4 vc = *(const float4*)(base + NT);

    float part = 0.0f;
    int r = 0;
    for (; r + 2 <= nrows; r += 2) {
        const float* p = base + (size_t)(r + 2) * NT;
        const float4 p0 = *(const float4*)(p);
        const float4 p1 = *(const float4*)(p + NT);
        float lf, rt;
        const long ro = (long)r * NT;
        halo(vc, needL, needR, pL, pR, ro, lf, rt);
        accum_row(cst[r],     vm, vc, p0, lf, rt, m0, m3, inv2dt, part);
        halo(p0, needL, needR, pL, pR, ro + NT, lf, rt);
        accum_row(cst[r + 1], vc, p0, p1, lf, rt, m0, m3, inv2dt, part);
        vm = p0; vc = p1;
    }
    if (r < nrows) {
        const float4 p0 = *(const float4*)(base + (size_t)(r + 2) * NT);
        float lf, rt;
        halo(vc, needL, needR, pL, pR, (long)r * NT, lf, rt);
        accum_row(cst[r], vm, vc, p0, lf, rt, m0, m3, inv2dt, part);
    }

    // ---- block reduce ----
    part = warp_reduce(part);
    edge = warp_reduce(edge);
    if ((tid & 31) == 0) { s1[tid >> 5] = part; s2[tid >> 5] = edge; }
    __syncthreads();
    if (tid < 32) {
        float vpp = (tid < 16) ? s1[tid] : 0.0f;
        float vee = (tid < 16) ? s2[tid] : 0.0f;
        vpp = warp_reduce(vpp);
        vee = warp_reduce(vee);
        if (tid == 0) {
            g_part[bid] = (double)vpp * W_PDE + (double)vee;
            __threadfence();
            s_old = atomicAdd(&g_count, 1u);
        }
    }
    __syncthreads();

    // ---- last block finishes: plain sum of 444 doubles ----
    if (s_old == NPDE - 1) {
        __threadfence();
        double v = (tid < NPDE) ? g_part[tid] : 0.0;
        v = warp_reduce_d(v);
        __shared__ double sd[16];
        if ((tid & 31) == 0) sd[tid >> 5] = v;
        __syncthreads();
        if (tid < 32) {
            double t2 = (tid < 16) ? sd[tid] : 0.0;
            t2 = warp_reduce_d(t2);
            if (tid == 0) {
                out[0] = (float)t2;
                g_count = 0;   // reset for next graph replay (deterministic)
            }
        }
    }
}

static double solve_depressed_cubic(double Q) {
    const double p = 6.0;             // CHI
    const double q = 6.0 * Q;
    const double sp = sqrt(p);
    double arg = fabs(q) / (2.0 * p * sp / (3.0 * sqrt(3.0)));
    if (arg < 1.0) arg = 1.0;
    const double c = 2.0 * sp * cosh(acosh(arg) / 3.0);
    return (q >= 0.0) ? -c : c;
}

extern "C" void kernel_launch(void* const* d_in, const int* in_sizes, int n_in,
                              void* d_out, int out_size)
{
    const float* V = (const float*)d_in[0];
    float* out = (float*)d_out;

    const double C1 = solve_depressed_cubic((100.0 - 0.0) / 30.0);
    const double C2 = solve_depressed_cubic((100.0 - 300.0) / 30.0);
    const double dL = C2 - C1;
    const float c1f = (float)C1;
    const float c2f = (float)C2;
    const float su_coef  = (float)(30.0 * dL);
    const float suu_coef = (float)(30.0 * dL * dL);
    const double TAU_MAX = 0.5 * 0.2 * 0.2 * 1.0;     // 0.02
    const double DT_NORM = TAU_MAX / (double)(NT - 1);
    const float inv2dt = (float)(1.0 / (2.0 * DT_NORM));

    loss_kernel<<<NPDE, 512>>>(V, out, c1f, c2f, su_coef, suu_coef, inv2dt);
}